// round 1
// baseline (speedup 1.0000x reference)
#include <cuda_runtime.h>
#include <math.h>

// DAGMixer: per-row gated mix.
//   logits[row] = dot(orig[row], W[0:H]) + dot(dag[row], W[H:2H]) + b
//   gate = sigmoid(logits)
//   mixed[row] = orig[row] + gate * (dag[row] - orig[row])
// Shapes: rows = B*T = 16384, H = 2048 (fp32).
//
// Strategy: one CTA per row, 256 threads. Each thread loads 2 float4 of orig
// and dag (8 floats each) into REGISTERS, computes the partial dot against W
// (L2-resident, 16KB), block-reduces, then mixes from registers and stores.
// Every HBM byte is touched exactly once -> ~403MB total traffic.

#define THREADS 256
#define H_DIM 2048
#define V4_PER_THREAD 2   // (H_DIM/4) / THREADS = 512/256

__global__ __launch_bounds__(THREADS, 8)
void dagmixer_kernel(const float* __restrict__ orig,
                     const float* __restrict__ dag,
                     const float* __restrict__ w,     // [2H]: W_o then W_d
                     const float* __restrict__ bgate, // [1]
                     float* __restrict__ mixed,       // [rows*H]
                     float* __restrict__ gate_out)    // [rows]
{
    const int row = blockIdx.x;
    const int tid = threadIdx.x;

    const float4* __restrict__ o4  = (const float4*)(orig + (size_t)row * H_DIM);
    const float4* __restrict__ d4  = (const float4*)(dag  + (size_t)row * H_DIM);
    const float4* __restrict__ wo4 = (const float4*)(w);
    const float4* __restrict__ wd4 = (const float4*)(w + H_DIM);

    float4 ov[V4_PER_THREAD];
    float4 dv[V4_PER_THREAD];
    float partial = 0.0f;

    #pragma unroll
    for (int k = 0; k < V4_PER_THREAD; k++) {
        const int idx = tid + k * THREADS;   // float4 index, coalesced
        ov[k] = o4[idx];
        dv[k] = d4[idx];
        const float4 a = wo4[idx];
        const float4 c = wd4[idx];
        partial += ov[k].x * a.x + ov[k].y * a.y + ov[k].z * a.z + ov[k].w * a.w;
        partial += dv[k].x * c.x + dv[k].y * c.y + dv[k].z * c.z + dv[k].w * c.w;
    }

    // Warp reduce
    #pragma unroll
    for (int off = 16; off > 0; off >>= 1)
        partial += __shfl_xor_sync(0xffffffff, partial, off);

    __shared__ float warpsum[THREADS / 32];
    __shared__ float gate_sh;
    const int wid  = tid >> 5;
    const int lane = tid & 31;
    if (lane == 0) warpsum[wid] = partial;
    __syncthreads();

    if (tid == 0) {
        float s = bgate[0];
        #pragma unroll
        for (int i = 0; i < THREADS / 32; i++) s += warpsum[i];
        const float g = 1.0f / (1.0f + expf(-s));
        gate_sh = g;
        gate_out[row] = g;
    }
    __syncthreads();

    const float g = gate_sh;
    float4* __restrict__ m4 = (float4*)(mixed + (size_t)row * H_DIM);

    #pragma unroll
    for (int k = 0; k < V4_PER_THREAD; k++) {
        const int idx = tid + k * THREADS;
        float4 r;
        r.x = ov[k].x + g * (dv[k].x - ov[k].x);
        r.y = ov[k].y + g * (dv[k].y - ov[k].y);
        r.z = ov[k].z + g * (dv[k].z - ov[k].z);
        r.w = ov[k].w + g * (dv[k].w - ov[k].w);
        m4[idx] = r;
    }
}

extern "C" void kernel_launch(void* const* d_in, const int* in_sizes, int n_in,
                              void* d_out, int out_size)
{
    const float* orig  = (const float*)d_in[0];  // original_hidden [B,T,H]
    const float* dag   = (const float*)d_in[1];  // dag_hidden      [B,T,H]
    const float* wgate = (const float*)d_in[2];  // W_gate          [2H,1]
    const float* bgate = (const float*)d_in[3];  // b_gate          [1]

    const int total = in_sizes[0];               // B*T*H
    const int rows  = total / H_DIM;             // B*T

    float* mixed    = (float*)d_out;             // first B*T*H floats
    float* gate_out = (float*)d_out + total;     // then B*T gate values

    dagmixer_kernel<<<rows, THREADS>>>(orig, dag, wgate, bgate, mixed, gate_out);
}